// round 16
// baseline (speedup 1.0000x reference)
#include <cuda_runtime.h>
#include <cuda_bf16.h>
#include <cstdint>

// Problem constants (fixed by the dataset)
#define BB   1024
#define TT   256
#define INDIM 128
#define HH   128
#define GG   384      // 3*H
#define HOR  24

// ---------------- scratch (device globals; no allocations allowed) ----------
__device__ float g_gx[(size_t)TT * BB * GG];        // 384 MB: x@w_i + b, [t][b][g]
__device__ float g_ys[(size_t)TT * BB * HH];        // 128 MB: hidden states, [t][b][j]
__device__ float g_W2[(size_t)TT * HH * HOR];       // 3 MB: folded weights, [t][j][p]
__device__ float g_bias_part[TT * HOR];
__device__ float g_final_bias[HOR];
__device__ __nv_bfloat16 g_whi[GG * INDIM];         // w_i^T hi, [n][k]
__device__ __nv_bfloat16 g_wlo[GG * INDIM];         // w_i^T lo, [n][k]
__device__ __nv_bfloat16 g_whh_hi[GG * HH];         // w_h^T hi, [n][k]
__device__ __nv_bfloat16 g_whh_lo[GG * HH];         // w_h^T lo, [n][k]

// ---------------- packed f32x2 helpers --------------------------------------
typedef unsigned long long u64;

__device__ __forceinline__ u64 dup2(float v) {
    u64 r; asm("mov.b64 %0, {%1, %1};" : "=l"(r) : "f"(v)); return r;
}
__device__ __forceinline__ void unpack2(u64 v, float& lo, float& hi) {
    asm("mov.b64 {%0, %1}, %2;" : "=f"(lo), "=f"(hi) : "l"(v));
}
__device__ __forceinline__ void ffma2(u64& d, u64 a, u64 b) {
    asm("fma.rn.f32x2 %0, %1, %2, %0;" : "+l"(d) : "l"(a), "l"(b));
}
__device__ __forceinline__ void fadd2(u64& d, u64 a) {
    asm("add.rn.f32x2 %0, %0, %1;" : "+l"(d) : "l"(a));
}
__device__ __forceinline__ u64 shfl_xor_u64(u64 v, int m) {
    uint32_t lo = (uint32_t)v, hi = (uint32_t)(v >> 32);
    lo = __shfl_xor_sync(0xffffffffu, lo, m);
    hi = __shfl_xor_sync(0xffffffffu, hi, m);
    return ((u64)hi << 32) | (u64)lo;
}

// ---------------- mma.sync / ldmatrix helpers (sm_100 baseline ISA) ----------
__device__ __forceinline__ uint32_t smem_u32(const void* p) {
    uint32_t a;
    asm("{ .reg .u64 t; cvta.to.shared.u64 t, %1; cvt.u32.u64 %0, t; }" : "=r"(a) : "l"(p));
    return a;
}
__device__ __forceinline__ void ldsm_x4(uint32_t* r, uint32_t addr) {
    asm volatile("ldmatrix.sync.aligned.m8n8.x4.shared.b16 {%0,%1,%2,%3}, [%4];"
                 : "=r"(r[0]), "=r"(r[1]), "=r"(r[2]), "=r"(r[3]) : "r"(addr));
}
__device__ __forceinline__ void ldsm_x2(uint32_t* r, uint32_t addr) {
    asm volatile("ldmatrix.sync.aligned.m8n8.x2.shared.b16 {%0,%1}, [%2];"
                 : "=r"(r[0]), "=r"(r[1]) : "r"(addr));
}
__device__ __forceinline__ void mma_bf16(float* d, const uint32_t* a,
                                         uint32_t b0, uint32_t b1) {
    asm volatile(
        "mma.sync.aligned.m16n8k16.row.col.f32.bf16.bf16.f32 "
        "{%0,%1,%2,%3}, {%4,%5,%6,%7}, {%8,%9}, {%0,%1,%2,%3};"
        : "+f"(d[0]), "+f"(d[1]), "+f"(d[2]), "+f"(d[3])
        : "r"(a[0]), "r"(a[1]), "r"(a[2]), "r"(a[3]), "r"(b0), "r"(b1));
}
__device__ __forceinline__ void cp_async16(uint32_t dst, const void* src) {
    asm volatile("cp.async.ca.shared.global [%0], [%1], 16;"
                 :: "r"(dst), "l"(src));
}
// swizzled byte offset, 256B rows (128 bf16), 16B chunks c16 in 0..15 (verified R10)
__device__ __forceinline__ uint32_t swz(int row, int c16) {
    return (uint32_t)(row * 256 + ((c16 ^ (row & 7)) << 4));
}
// swizzled byte offset, 128B rows (64 bf16), chunks 0..7 (verified R13)
__device__ __forceinline__ uint32_t swz128(int row, int c16) {
    return (uint32_t)(row * 128 + ((c16 ^ (row & 7)) << 4));
}

// ---------------- activation helpers ----------------------------------------
__device__ __forceinline__ float sigmoid_f(float x) {
    return 1.0f / (1.0f + __expf(-x));
}
__device__ __forceinline__ float tanh_f(float x) {
    float ax = fabsf(x);
    float e  = __expf(2.0f * ax);
    float r  = 1.0f - 2.0f / (e + 1.0f);
    return copysignf(r, x);
}

// bf16 hi/lo split of a value pair, stored swizzled (256B-row tile layout).
__device__ __forceinline__ void bsplit_store(char* smemc, int hiOff, int loOff,
                                             int row, int col, float v0, float v1) {
    __nv_bfloat162 h = __floats2bfloat162_rn(v0, v1);
    float l0 = v0 - __bfloat162float(h.x);
    float l1 = v1 - __bfloat162float(h.y);
    __nv_bfloat162 l = __floats2bfloat162_rn(l0, l1);
    int byte = 2 * col;   // col even -> 4B aligned
    uint32_t adr = (uint32_t)(row * 256 + ((((byte >> 4) ^ (row & 7)) << 4) | (byte & 15)));
    *(uint32_t*)(smemc + hiOff + adr) = *(uint32_t*)&h;
    *(uint32_t*)(smemc + loOff + adr) = *(uint32_t*)&l;
}

// ============================================================================
// Kernel 1: fold  W2_t = mlp_w @ (fc_w_t @ out_w)  and bias partial per t.
// ============================================================================
__global__ void __launch_bounds__(256) w2_kernel(
    const float* __restrict__ mlp_w,   // [128,512]
    const float* __restrict__ mlp_b,   // [512]
    const float* __restrict__ fc_w,    // [131072,128]
    const float* __restrict__ out_w)   // [128,24]
{
    extern __shared__ float sm[];
    float* ows    = sm;
    float* P      = sm + 3072;
    float* rowbuf = sm + 3072 + 12288;
    const int tid  = threadIdx.x;
    const int t    = blockIdx.x;
    const int warp = tid >> 5;
    const int lane = tid & 31;

    for (int i = tid; i < HH * HOR; i += 256) ows[i] = out_w[i];
    __syncthreads();

    const float* fcb = fc_w + (size_t)t * 512 * HH;
    for (int j = warp; j < 512; j += 8) {
        float4 v = ((const float4*)(fcb + (size_t)j * HH))[lane];
        ((float4*)(rowbuf + warp * 128))[lane] = v;
        __syncwarp();
        if (lane < HOR) {
            const float* rb = rowbuf + warp * 128;
            float a0 = 0.0f, a1 = 0.0f, a2 = 0.0f, a3 = 0.0f;
            #pragma unroll 8
            for (int k = 0; k < 32; k++) {
                a0 = fmaf(rb[k],      ows[(k)      * HOR + lane], a0);
                a1 = fmaf(rb[k + 32], ows[(k + 32) * HOR + lane], a1);
                a2 = fmaf(rb[k + 64], ows[(k + 64) * HOR + lane], a2);
                a3 = fmaf(rb[k + 96], ows[(k + 96) * HOR + lane], a3);
            }
            P[j * HOR + lane] = ((a0 + a1) + a2) + a3;
        }
        __syncwarp();
    }
    __syncthreads();

    if (warp == 0 && lane < HOR) {
        float acc = 0.0f;
        for (int j = 0; j < 512; j++) acc = fmaf(mlp_b[j], P[j * HOR + lane], acc);
        g_bias_part[t * HOR + lane] = acc;
    }

    const int i  = tid & 127;
    const int p0 = (tid >> 7) * 12;
    float acc[12];
    #pragma unroll
    for (int q = 0; q < 12; q++) acc[q] = 0.0f;
    const float* mw = mlp_w + (size_t)i * 512;
    for (int j = 0; j < 512; j++) {
        float m = mw[j];
        const float* pr = P + j * HOR + p0;
        #pragma unroll
        for (int q = 0; q < 12; q++) acc[q] = fmaf(m, pr[q], acc[q]);
    }
    float* dst = g_W2 + ((size_t)t * HH + i) * HOR + p0;
    #pragma unroll
    for (int q = 0; q < 12; q++) dst[q] = acc[q];
}

// ============================================================================
// Kernel 2: final bias = sum_t bias_part + fc_b@out_w + out_b
// ============================================================================
__global__ void bias_final_kernel(const float* __restrict__ fc_b,
                                  const float* __restrict__ out_w,
                                  const float* __restrict__ out_b)
{
    int p = threadIdx.x;
    if (p >= HOR) return;
    float s = out_b[p];
    for (int t = 0; t < TT; t++) s += g_bias_part[t * HOR + p];
    for (int o = 0; o < HH; o++) s = fmaf(fc_b[o], out_w[o * HOR + p], s);
    g_final_bias[p] = s;
}

// ============================================================================
// Kernel 2b/2c: split w_i and w_h into bf16 hi/lo, transposed to [n][k].
// ============================================================================
__global__ void wsplit_kernel(const float* __restrict__ w_i)  // [128k][384n]
{
    int n = blockIdx.x;
    int k = threadIdx.x;
    float v = w_i[(size_t)k * GG + n];
    __nv_bfloat16 h = __float2bfloat16(v);
    g_whi[n * INDIM + k] = h;
    g_wlo[n * INDIM + k] = __float2bfloat16(v - __bfloat162float(h));
}
__global__ void whhsplit_kernel(const float* __restrict__ w_h)  // [128k][384n]
{
    int n = blockIdx.x;
    int k = threadIdx.x;
    float v = w_h[(size_t)k * GG + n];
    __nv_bfloat16 h = __float2bfloat16(v);
    g_whh_hi[n * HH + k] = h;
    g_whh_lo[n * HH + k] = __float2bfloat16(v - __bfloat162float(h));
}

// ============================================================================
// Kernel 3 (v10, unchanged): gx via fused 3-term mma.sync, K-split staging.
// ============================================================================
#define GXK_A_HI  0
#define GXK_A_LO  16384
#define GXK_B_HI  32768
#define GXK_B_LO  49152
#define GXK_SMEM  65536

__global__ void __launch_bounds__(256, 2) gx_mma_kernel(
    const float* __restrict__ x,     // [B][T][128] == [m][128]
    const float* __restrict__ bvec)  // [384]
{
    extern __shared__ char smemc[];
    const int tid  = threadIdx.x;
    const int wid  = tid >> 5;
    const int lane = tid & 31;
    const int gate = blockIdx.x % 3;
    const int m0g  = (blockIdx.x / 3) * 128;
    uint32_t sbase = smem_u32(smemc);

    const int m0w = (wid & 3) * 32;
    const int n0w = (wid >> 2) * 64;
    const int lr  = lane & 15;
    const int lc  = lane >> 4;

    float acc[2][8][4];
    #pragma unroll
    for (int mi = 0; mi < 2; mi++)
        #pragma unroll
        for (int nt = 0; nt < 8; nt++)
            #pragma unroll
            for (int q = 0; q < 4; q++) acc[mi][nt][q] = 0.0f;

    const int srow = tid >> 1;
    const int shalf = tid & 1;

    #pragma unroll 1
    for (int ph = 0; ph < 2; ph++) {
        {
            size_t src = (size_t)(gate * 128 + srow) * INDIM + ph * 64 + shalf * 32;
            const char* bh = (const char*)(g_whi + src);
            const char* bl = (const char*)(g_wlo + src);
            #pragma unroll
            for (int u = 0; u < 4; u++) {
                uint32_t o = swz128(srow, shalf * 4 + u);
                cp_async16(sbase + GXK_B_HI + o, bh + u * 16);
                cp_async16(sbase + GXK_B_LO + o, bl + u * 16);
            }
            asm volatile("cp.async.commit_group;" ::: "memory");
        }
        {
            const float4* xr = (const float4*)(x + (size_t)(m0g + srow) * INDIM
                                               + ph * 64 + shalf * 32);
            #pragma unroll
            for (int u = 0; u < 4; u++) {
                float4 a = xr[2 * u], b = xr[2 * u + 1];
                float f[8] = {a.x, a.y, a.z, a.w, b.x, b.y, b.z, b.w};
                uint32_t hi[4], lo[4];
                #pragma unroll
                for (int p = 0; p < 4; p++) {
                    __nv_bfloat162 h = __floats2bfloat162_rn(f[2*p], f[2*p+1]);
                    hi[p] = *(uint32_t*)&h;
                    float l0 = f[2*p]     - __bfloat162float(h.x);
                    float l1 = f[2*p + 1] - __bfloat162float(h.y);
                    __nv_bfloat162 l = __floats2bfloat162_rn(l0, l1);
                    lo[p] = *(uint32_t*)&l;
                }
                uint32_t o = swz128(srow, shalf * 4 + u);
                *(uint4*)(smemc + GXK_A_HI + o) = make_uint4(hi[0], hi[1], hi[2], hi[3]);
                *(uint4*)(smemc + GXK_A_LO + o) = make_uint4(lo[0], lo[1], lo[2], lo[3]);
            }
        }
        asm volatile("cp.async.wait_group 0;" ::: "memory");
        __syncthreads();

        #pragma unroll
        for (int s = 0; s < 4; s++) {
            const int c16 = 2 * s + lc;
            const int ra  = m0w + lr;

            uint32_t a0[4], a1[4];
            ldsm_x4(a0, sbase + GXK_A_HI + swz128(ra, c16));
            ldsm_x4(a1, sbase + GXK_A_HI + swz128(ra + 16, c16));

            uint32_t bh[4][4];
            #pragma unroll
            for (int q = 0; q < 4; q++)
                ldsm_x4(bh[q], sbase + GXK_B_HI + swz128(n0w + q * 16 + lr, c16));

            #pragma unroll
            for (int nt = 0; nt < 8; nt++) {
                int q = nt >> 1, sel = nt & 1;
                mma_bf16(acc[0][nt], a0, bh[q][sel], bh[q][sel + 2]);
                mma_bf16(acc[1][nt], a1, bh[q][sel], bh[q][sel + 2]);
            }
            {
                uint32_t bl[4][4];
                #pragma unroll
                for (int q = 0; q < 4; q++)
                    ldsm_x4(bl[q], sbase + GXK_B_LO + swz128(n0w + q * 16 + lr, c16));
                #pragma unroll
                for (int nt = 0; nt < 8; nt++) {
                    int q = nt >> 1, sel = nt & 1;
                    mma_bf16(acc[0][nt], a0, bl[q][sel], bl[q][sel + 2]);
                    mma_bf16(acc[1][nt], a1, bl[q][sel], bl[q][sel + 2]);
                }
            }
            {
                uint32_t l0[4], l1[4];
                ldsm_x4(l0, sbase + GXK_A_LO + swz128(ra, c16));
                ldsm_x4(l1, sbase + GXK_A_LO + swz128(ra + 16, c16));
                #pragma unroll
                for (int nt = 0; nt < 8; nt++) {
                    int q = nt >> 1, sel = nt & 1;
                    mma_bf16(acc[0][nt], l0, bh[q][sel], bh[q][sel + 2]);
                    mma_bf16(acc[1][nt], l1, bh[q][sel], bh[q][sel + 2]);
                }
            }
        }
        if (ph == 0) __syncthreads();
    }

    const int colq = (lane & 3) * 2;
    #pragma unroll
    for (int nt = 0; nt < 8; nt++) {
        int c = n0w + nt * 8 + colq;
        float2 bv = *(const float2*)(bvec + gate * 128 + c);
        #pragma unroll
        for (int mi = 0; mi < 2; mi++) {
            int gm0 = m0g + m0w + 16 * mi + (lane >> 2);
            #pragma unroll
            for (int h = 0; h < 2; h++) {
                int gm = gm0 + 8 * h;
                int tt = gm & 255, bb = gm >> 8;
                float2 o;
                o.x = acc[mi][nt][2 * h + 0] + bv.x;
                o.y = acc[mi][nt][2 * h + 1] + bv.y;
                *(float2*)(g_gx + ((size_t)tt * BB + bb) * GG + gate * 128 + c) = o;
            }
        }
    }
}

// ============================================================================
// Kernel 4 (v10 = rec_tc3): tensor-core recurrence, B FRAGMENTS HOISTED TO
// REGISTERS (step-invariant whh: zero per-step B ldsm) and A loads via
// ldmatrix.x2 over the 8 valid rows only (rows 8-15 = zero registers).
// Per-warp per-step ldsm: 64 x4 -> 32 x2 (4x fewer L1 wavefronts).
// Layout/indexing otherwise identical to verified v8/v9.
// ============================================================================
#define RT_B_HI  0          // 384*256 = 98304
#define RT_B_LO  98304
#define RT_HHI   196608     // 16x128 bf16 = 4096
#define RT_HLO   200704
#define RT_RHHI  204800
#define RT_RHLO  208896
#define RT_H32   212992     // 8*128 f32 = 4096
#define RT_ZS    217088     // 128*8 f32 = 4096
#define RT_SMEM  221184

__global__ void __launch_bounds__(512, 1) rec_tc_kernel()
{
    extern __shared__ char smemc[];
    uint32_t sb = smem_u32(smemc);
    float* h32 = (float*)(smemc + RT_H32);
    float* zsf = (float*)(smemc + RT_ZS);
    const int tid  = threadIdx.x;
    const int wid  = tid >> 5;
    const int lane = tid & 31;
    const int b0   = blockIdx.x * 8;

    // ---- stage static B = whh hi/lo, swizzled (rows 384 x 256B) ----
    for (int idx = tid; idx < 384 * 16; idx += 512) {
        int r = idx >> 4, c = idx & 15;
        uint32_t o = swz(r, c);
        cp_async16(sb + RT_B_HI + o, (const char*)g_whh_hi + (size_t)r * 256 + c * 16);
        cp_async16(sb + RT_B_LO + o, (const char*)g_whh_lo + (size_t)r * 256 + c * 16);
    }
    asm volatile("cp.async.commit_group;" ::: "memory");
    for (int idx = tid; idx < 1024; idx += 512) {
        ((uint32_t*)(smemc + RT_HHI))[idx]  = 0;
        ((uint32_t*)(smemc + RT_HLO))[idx]  = 0;
        ((uint32_t*)(smemc + RT_RHHI))[idx] = 0;
        ((uint32_t*)(smemc + RT_RHLO))[idx] = 0;
        h32[idx] = 0.0f;
    }
    asm volatile("cp.async.wait_group 0;" ::: "memory");
    __syncthreads();

    const int lr    = lane & 15;
    const int lc    = lane >> 4;
    const int lane8 = lane & 7;
    const int ksel  = (lane >> 3) & 1;   // x2 chunk selector
    const int row   = lane >> 2;
    const int cp2   = 2 * (lane & 3);
    const int n0z   = wid * 16;
    const int n0a   = 256 + wid * 8;
    const int acol  = wid * 8 + cp2;
    const int jz    = n0z - 128;
    const uint32_t ZR = 0;

    // ---- hoist step-invariant B fragments into registers ----
    uint32_t Bzh[8][4], Bzl[8][4];   // zr phase: n16 x k16 per kstep
    uint32_t Bah[8][2], Bal[8][2];   // a phase: n8 x k16 (x2: only tiles used)
    #pragma unroll
    for (int s = 0; s < 8; s++) {
        int c16 = 2 * s + lc;
        ldsm_x4(Bzh[s], sb + RT_B_HI + swz(n0z + lr, c16));
        ldsm_x4(Bzl[s], sb + RT_B_LO + swz(n0z + lr, c16));
        uint32_t a2 = swz(n0a + lane8, 2 * s + ksel);
        ldsm_x2(Bah[s], sb + RT_B_HI + a2);
        ldsm_x2(Bal[s], sb + RT_B_LO + a2);
    }

    // gx pipeline registers
    float2 gz0, gz1, ga;
    {
        const float* g0 = g_gx + (size_t)b0 * GG;
        gz0 = *(const float2*)(g0 + row * GG + n0z + cp2);
        gz1 = *(const float2*)(g0 + row * GG + n0z + 8 + cp2);
        ga  = *(const float2*)(g0 + row * GG + 256 + acol);
    }

    for (int t = 0; t < TT; t++) {
        // ---- zr MMA: A via x2 (8 valid rows), B from registers ----
        float azh[2][4], azl[2][4], azm[2][4];
        #pragma unroll
        for (int nt = 0; nt < 2; nt++)
            #pragma unroll
            for (int q = 0; q < 4; q++) { azh[nt][q] = 0.0f; azl[nt][q] = 0.0f; azm[nt][q] = 0.0f; }

        #pragma unroll
        for (int s = 0; s < 8; s++) {
            uint32_t a2 = swz(lane8, 2 * s + ksel);
            uint32_t ah2[2], al2[2];
            ldsm_x2(ah2, sb + RT_HHI + a2);
            ldsm_x2(al2, sb + RT_HLO + a2);
            uint32_t ahF[4] = {ah2[0], ZR, ah2[1], ZR};
            uint32_t alF[4] = {al2[0], ZR, al2[1], ZR};
            #pragma unroll
            for (int nt = 0; nt < 2; nt++) {
                mma_bf16(azh[nt], ahF, Bzh[s][nt], Bzh[s][nt + 2]);   // hh
                mma_bf16(azl[nt], ahF, Bzl[s][nt], Bzl[s][nt + 2]);   // hl
                mma_bf16(azm[nt], alF, Bzh[s][nt], Bzh[s][nt + 2]);   // lh
            }
        }
        {
            float v00 = ((azh[0][0] + azl[0][0]) + azm[0][0]) + gz0.x;
            float v01 = ((azh[0][1] + azl[0][1]) + azm[0][1]) + gz0.y;
            float v10 = ((azh[1][0] + azl[1][0]) + azm[1][0]) + gz1.x;
            float v11 = ((azh[1][1] + azl[1][1]) + azm[1][1]) + gz1.y;
            if (wid < 8) {                       // z gate
                zsf[(n0z + cp2)         * 8 + row] = sigmoid_f(v00);
                zsf[(n0z + cp2 + 1)     * 8 + row] = sigmoid_f(v01);
                zsf[(n0z + 8 + cp2)     * 8 + row] = sigmoid_f(v10);
                zsf[(n0z + 8 + cp2 + 1) * 8 + row] = sigmoid_f(v11);
            } else {                             // r gate -> rh = r .* h
                float2 h0 = *(const float2*)&h32[row * 128 + jz + cp2];
                float2 h1 = *(const float2*)&h32[row * 128 + jz + 8 + cp2];
                float r00 = sigmoid_f(v00) * h0.x, r01 = sigmoid_f(v01) * h0.y;
                float r10 = sigmoid_f(v10) * h1.x, r11 = sigmoid_f(v11) * h1.y;
                bsplit_store(smemc, RT_RHHI, RT_RHLO, row, jz + cp2,     r00, r01);
                bsplit_store(smemc, RT_RHHI, RT_RHLO, row, jz + 8 + cp2, r10, r11);
            }
        }
        __syncthreads();

        // prefetch gx for step t+1 (covered by phase-2 region)
        float2 gz0n, gz1n, gan;
        if (t + 1 < TT) {
            const float* gn = g_gx + ((size_t)(t + 1) * BB + b0) * GG;
            gz0n = *(const float2*)(gn + row * GG + n0z + cp2);
            gz1n = *(const float2*)(gn + row * GG + n0z + 8 + cp2);
            gan  = *(const float2*)(gn + row * GG + 256 + acol);
        }

        // ---- a-gate MMA: A via x2, B from registers ----
        float aah[4] = {0,0,0,0}, aal[4] = {0,0,0,0}, aam[4] = {0,0,0,0};
        #pragma unroll
        for (int s = 0; s < 8; s++) {
            uint32_t a2 = swz(lane8, 2 * s + ksel);
            uint32_t rh2[2], rl2[2];
            ldsm_x2(rh2, sb + RT_RHHI + a2);
            ldsm_x2(rl2, sb + RT_RHLO + a2);
            uint32_t rhF[4] = {rh2[0], ZR, rh2[1], ZR};
            uint32_t rlF[4] = {rl2[0], ZR, rl2[1], ZR};
            mma_bf16(aah, rhF, Bah[s][0], Bah[s][1]);
            mma_bf16(aal, rhF, Bal[s][0], Bal[s][1]);
            mma_bf16(aam, rlF, Bah[s][0], Bah[s][1]);
        }
        {
            float s0 = ((aah[0] + aal[0]) + aam[0]) + ga.x;
            float s1 = ((aah[1] + aal[1]) + aam[1]) + ga.y;
            float a0 = tanh_f(s0);
            float a1 = tanh_f(s1);
            float z0 = zsf[(acol)     * 8 + row];
            float z1 = zsf[(acol + 1) * 8 + row];
            float2 hv = *(const float2*)&h32[row * 128 + acol];
            float hn0 = fmaf(z0, a0 - hv.x, hv.x);
            float hn1 = fmaf(z1, a1 - hv.y, hv.y);
            *(float2*)&h32[row * 128 + acol] = make_float2(hn0, hn1);
            bsplit_store(smemc, RT_HHI, RT_HLO, row, acol, hn0, hn1);
            *(float2*)&g_ys[((size_t)t * BB + b0 + row) * HH + acol] = make_float2(hn0, hn1);
        }
        gz0 = gz0n; gz1 = gz1n; ga = gan;
        __syncthreads();
    }
}

// ============================================================================
// Kernel 5 (unchanged): out[b,p] = sum_t sum_j ys[t,b,j]*W2[t,j,p] + bias.
// ============================================================================
__global__ void __launch_bounds__(512, 1) fc_kernel(float* __restrict__ out)
{
    __shared__ float red[8 * HOR * 4];

    const int tid = threadIdx.x;
    const int j   = tid & 127;
    const int g   = tid >> 7;
    const int b0  = blockIdx.x * 8;
    const int lane = tid & 31;
    const int jblk = (j >> 5);

    u64 acc[2][12];
    #pragma unroll
    for (int u = 0; u < 2; u++)
        #pragma unroll
        for (int q = 0; q < 12; q++) acc[u][q] = 0ULL;

    #pragma unroll 2
    for (int t = 0; t < TT; t++) {
        const float* ysp = g_ys + ((size_t)t * BB + b0 + 2 * g) * HH + j;
        float y0 = __ldg(ysp);
        float y1 = __ldg(ysp + HH);
        const ulonglong2* wp = (const ulonglong2*)(g_W2 + ((size_t)t * HH + j) * HOR);
        ulonglong2 w0 = wp[0], w1 = wp[1], w2 = wp[2],
                   w3 = wp[3], w4 = wp[4], w5 = wp[5];
        u64 wq[12] = {w0.x, w0.y, w1.x, w1.y, w2.x, w2.y,
                      w3.x, w3.y, w4.x, w4.y, w5.x, w5.y};
        u64 y0d = dup2(y0), y1d = dup2(y1);
        #pragma unroll
        for (int q = 0; q < 12; q++) {
            ffma2(acc[0][q], y0d, wq[q]);
            ffma2(acc[1][q], y1d, wq[q]);
        }
    }

    #pragma unroll
    for (int u = 0; u < 2; u++)
        #pragma unroll
        for (int q = 0; q < 12; q++) {
            fadd2(acc[u][q], shfl_xor_u64(acc[u][q], 1));
            fadd2(acc[u][q], shfl_xor_u64(acc[u][q], 2));
            fadd2(acc[u][q], shfl_xor_u64(acc[u][q], 4));
            fadd2(acc[u][q], shfl_xor_u64(acc[u][q], 8));
            fadd2(acc[u][q], shfl_xor_u64(acc[u][q], 16));
        }

    if (lane == 0) {
        #pragma unroll
        for (int u = 0; u < 2; u++) {
            int rrow = 2 * g + u;
            #pragma unroll
            for (int q = 0; q < 12; q++) {
                float v0, v1;
                unpack2(acc[u][q], v0, v1);
                red[(rrow * HOR + 2 * q + 0) * 4 + jblk] = v0;
                red[(rrow * HOR + 2 * q + 1) * 4 + jblk] = v1;
            }
        }
    }
    __syncthreads();

    if (tid < 8 * HOR) {
        int rrow = tid / HOR;
        int p    = tid - rrow * HOR;
        const float* pp = red + (rrow * HOR + p) * 4;
        float s = ((pp[0] + pp[1]) + pp[2]) + pp[3];
        out[(size_t)(b0 + rrow) * HOR + p] = s + g_final_bias[p];
    }
}

// ============================================================================
// launch
// ============================================================================
extern "C" void kernel_launch(void* const* d_in, const int* in_sizes, int n_in,
                              void* d_out, int out_size)
{
    const float* x     = (const float*)d_in[0];
    const float* w_i   = (const float*)d_in[1];
    const float* w_h   = (const float*)d_in[2];
    const float* bvec  = (const float*)d_in[3];
    const float* mlp_w = (const float*)d_in[4];
    const float* mlp_b = (const float*)d_in[5];
    const float* fc_w  = (const float*)d_in[6];
    const float* fc_b  = (const float*)d_in[7];
    const float* out_w = (const float*)d_in[8];
    const float* out_b = (const float*)d_in[9];
    float* out = (float*)d_out;

    const int smem_w2 = (3072 + 12288 + 1024) * 4;   // 65536

    cudaFuncSetAttribute(w2_kernel,     cudaFuncAttributeMaxDynamicSharedMemorySize, smem_w2);
    cudaFuncSetAttribute(gx_mma_kernel, cudaFuncAttributeMaxDynamicSharedMemorySize, GXK_SMEM);
    cudaFuncSetAttribute(rec_tc_kernel, cudaFuncAttributeMaxDynamicSharedMemorySize, RT_SMEM);

    w2_kernel<<<TT, 256, smem_w2>>>(mlp_w, mlp_b, fc_w, out_w);
    bias_final_kernel<<<1, 32>>>(fc_b, out_w, out_b);
    wsplit_kernel<<<GG, 128>>>(w_i);
    whhsplit_kernel<<<GG, 128>>>(w_h);
    gx_mma_kernel<<<(BB * TT / 128) * 3, 256, GXK_SMEM>>>(x, bvec);
    rec_tc_kernel<<<BB / 8, 512, RT_SMEM>>>();
    fc_kernel<<<BB / 8, 512>>>(out);
}

// round 17
// speedup vs baseline: 1.1350x; 1.1350x over previous
#include <cuda_runtime.h>
#include <cuda_bf16.h>
#include <cstdint>

// Problem constants (fixed by the dataset)
#define BB   1024
#define TT   256
#define INDIM 128
#define HH   128
#define GG   384      // 3*H
#define HOR  24

// ---------------- scratch (device globals; no allocations allowed) ----------
__device__ float g_gx[(size_t)TT * BB * GG];        // 384 MB: x@w_i + b, [t][b][g]
__device__ float g_ys[(size_t)TT * BB * HH];        // 128 MB: hidden states, [t][b][j]
__device__ float g_W2[(size_t)TT * HH * HOR];       // 3 MB: folded weights, [t][j][p]
__device__ float g_bias_part[TT * HOR];
__device__ float g_final_bias[HOR];
__device__ __nv_bfloat16 g_whi[GG * INDIM];         // w_i^T hi, [n][k]
__device__ __nv_bfloat16 g_wlo[GG * INDIM];         // w_i^T lo, [n][k]
__device__ __nv_bfloat16 g_whh_hi[GG * HH];         // w_h^T hi, [n][k]
__device__ __nv_bfloat16 g_whh_lo[GG * HH];         // w_h^T lo, [n][k]

// ---------------- packed f32x2 helpers --------------------------------------
typedef unsigned long long u64;

__device__ __forceinline__ u64 dup2(float v) {
    u64 r; asm("mov.b64 %0, {%1, %1};" : "=l"(r) : "f"(v)); return r;
}
__device__ __forceinline__ void unpack2(u64 v, float& lo, float& hi) {
    asm("mov.b64 {%0, %1}, %2;" : "=f"(lo), "=f"(hi) : "l"(v));
}
__device__ __forceinline__ void ffma2(u64& d, u64 a, u64 b) {
    asm("fma.rn.f32x2 %0, %1, %2, %0;" : "+l"(d) : "l"(a), "l"(b));
}
__device__ __forceinline__ void fadd2(u64& d, u64 a) {
    asm("add.rn.f32x2 %0, %0, %1;" : "+l"(d) : "l"(a));
}
__device__ __forceinline__ u64 shfl_xor_u64(u64 v, int m) {
    uint32_t lo = (uint32_t)v, hi = (uint32_t)(v >> 32);
    lo = __shfl_xor_sync(0xffffffffu, lo, m);
    hi = __shfl_xor_sync(0xffffffffu, hi, m);
    return ((u64)hi << 32) | (u64)lo;
}

// ---------------- mma.sync / ldmatrix helpers (sm_100 baseline ISA) ----------
__device__ __forceinline__ uint32_t smem_u32(const void* p) {
    uint32_t a;
    asm("{ .reg .u64 t; cvta.to.shared.u64 t, %1; cvt.u32.u64 %0, t; }" : "=r"(a) : "l"(p));
    return a;
}
__device__ __forceinline__ void ldsm_x4(uint32_t* r, uint32_t addr) {
    asm volatile("ldmatrix.sync.aligned.m8n8.x4.shared.b16 {%0,%1,%2,%3}, [%4];"
                 : "=r"(r[0]), "=r"(r[1]), "=r"(r[2]), "=r"(r[3]) : "r"(addr));
}
__device__ __forceinline__ void ldsm_x2(uint32_t* r, uint32_t addr) {
    asm volatile("ldmatrix.sync.aligned.m8n8.x2.shared.b16 {%0,%1}, [%2];"
                 : "=r"(r[0]), "=r"(r[1]) : "r"(addr));
}
__device__ __forceinline__ void mma_bf16(float* d, const uint32_t* a,
                                         uint32_t b0, uint32_t b1) {
    asm volatile(
        "mma.sync.aligned.m16n8k16.row.col.f32.bf16.bf16.f32 "
        "{%0,%1,%2,%3}, {%4,%5,%6,%7}, {%8,%9}, {%0,%1,%2,%3};"
        : "+f"(d[0]), "+f"(d[1]), "+f"(d[2]), "+f"(d[3])
        : "r"(a[0]), "r"(a[1]), "r"(a[2]), "r"(a[3]), "r"(b0), "r"(b1));
}
__device__ __forceinline__ void cp_async16(uint32_t dst, const void* src) {
    asm volatile("cp.async.ca.shared.global [%0], [%1], 16;"
                 :: "r"(dst), "l"(src));
}
// swizzled byte offset, 256B rows (128 bf16), 16B chunks c16 in 0..15 (verified R10)
__device__ __forceinline__ uint32_t swz(int row, int c16) {
    return (uint32_t)(row * 256 + ((c16 ^ (row & 7)) << 4));
}
// swizzled byte offset, 128B rows (64 bf16), chunks 0..7 (verified R13)
__device__ __forceinline__ uint32_t swz128(int row, int c16) {
    return (uint32_t)(row * 128 + ((c16 ^ (row & 7)) << 4));
}

// ---------------- activation helpers ----------------------------------------
__device__ __forceinline__ float sigmoid_f(float x) {
    return 1.0f / (1.0f + __expf(-x));
}
__device__ __forceinline__ float tanh_f(float x) {
    float ax = fabsf(x);
    float e  = __expf(2.0f * ax);
    float r  = 1.0f - 2.0f / (e + 1.0f);
    return copysignf(r, x);
}

// bf16 hi/lo split of a value pair, stored into a STACKED 16-row tile:
// hi at row, lo at row+8 (same swizzled column pattern: swz uses row&7).
__device__ __forceinline__ void bsplit_store_stacked(char* smemc, int off,
                                                     int row, int col,
                                                     float v0, float v1) {
    __nv_bfloat162 h = __floats2bfloat162_rn(v0, v1);
    float l0 = v0 - __bfloat162float(h.x);
    float l1 = v1 - __bfloat162float(h.y);
    __nv_bfloat162 l = __floats2bfloat162_rn(l0, l1);
    int byte = 2 * col;   // col even -> 4B aligned
    uint32_t adr = (uint32_t)(row * 256 + ((((byte >> 4) ^ (row & 7)) << 4) | (byte & 15)));
    *(uint32_t*)(smemc + off + adr)        = *(uint32_t*)&h;
    *(uint32_t*)(smemc + off + adr + 2048) = *(uint32_t*)&l;   // row+8 -> +8*256
}

// ============================================================================
// Kernel 1: fold  W2_t = mlp_w @ (fc_w_t @ out_w)  and bias partial per t.
// ============================================================================
__global__ void __launch_bounds__(256) w2_kernel(
    const float* __restrict__ mlp_w,   // [128,512]
    const float* __restrict__ mlp_b,   // [512]
    const float* __restrict__ fc_w,    // [131072,128]
    const float* __restrict__ out_w)   // [128,24]
{
    extern __shared__ float sm[];
    float* ows    = sm;
    float* P      = sm + 3072;
    float* rowbuf = sm + 3072 + 12288;
    const int tid  = threadIdx.x;
    const int t    = blockIdx.x;
    const int warp = tid >> 5;
    const int lane = tid & 31;

    for (int i = tid; i < HH * HOR; i += 256) ows[i] = out_w[i];
    __syncthreads();

    const float* fcb = fc_w + (size_t)t * 512 * HH;
    for (int j = warp; j < 512; j += 8) {
        float4 v = ((const float4*)(fcb + (size_t)j * HH))[lane];
        ((float4*)(rowbuf + warp * 128))[lane] = v;
        __syncwarp();
        if (lane < HOR) {
            const float* rb = rowbuf + warp * 128;
            float a0 = 0.0f, a1 = 0.0f, a2 = 0.0f, a3 = 0.0f;
            #pragma unroll 8
            for (int k = 0; k < 32; k++) {
                a0 = fmaf(rb[k],      ows[(k)      * HOR + lane], a0);
                a1 = fmaf(rb[k + 32], ows[(k + 32) * HOR + lane], a1);
                a2 = fmaf(rb[k + 64], ows[(k + 64) * HOR + lane], a2);
                a3 = fmaf(rb[k + 96], ows[(k + 96) * HOR + lane], a3);
            }
            P[j * HOR + lane] = ((a0 + a1) + a2) + a3;
        }
        __syncwarp();
    }
    __syncthreads();

    if (warp == 0 && lane < HOR) {
        float acc = 0.0f;
        for (int j = 0; j < 512; j++) acc = fmaf(mlp_b[j], P[j * HOR + lane], acc);
        g_bias_part[t * HOR + lane] = acc;
    }

    const int i  = tid & 127;
    const int p0 = (tid >> 7) * 12;
    float acc[12];
    #pragma unroll
    for (int q = 0; q < 12; q++) acc[q] = 0.0f;
    const float* mw = mlp_w + (size_t)i * 512;
    for (int j = 0; j < 512; j++) {
        float m = mw[j];
        const float* pr = P + j * HOR + p0;
        #pragma unroll
        for (int q = 0; q < 12; q++) acc[q] = fmaf(m, pr[q], acc[q]);
    }
    float* dst = g_W2 + ((size_t)t * HH + i) * HOR + p0;
    #pragma unroll
    for (int q = 0; q < 12; q++) dst[q] = acc[q];
}

// ============================================================================
// Kernel 2: final bias = sum_t bias_part + fc_b@out_w + out_b
// ============================================================================
__global__ void bias_final_kernel(const float* __restrict__ fc_b,
                                  const float* __restrict__ out_w,
                                  const float* __restrict__ out_b)
{
    int p = threadIdx.x;
    if (p >= HOR) return;
    float s = out_b[p];
    for (int t = 0; t < TT; t++) s += g_bias_part[t * HOR + p];
    for (int o = 0; o < HH; o++) s = fmaf(fc_b[o], out_w[o * HOR + p], s);
    g_final_bias[p] = s;
}

// ============================================================================
// Kernel 2b/2c: split w_i and w_h into bf16 hi/lo, transposed to [n][k].
// ============================================================================
__global__ void wsplit_kernel(const float* __restrict__ w_i)  // [128k][384n]
{
    int n = blockIdx.x;
    int k = threadIdx.x;
    float v = w_i[(size_t)k * GG + n];
    __nv_bfloat16 h = __float2bfloat16(v);
    g_whi[n * INDIM + k] = h;
    g_wlo[n * INDIM + k] = __float2bfloat16(v - __bfloat162float(h));
}
__global__ void whhsplit_kernel(const float* __restrict__ w_h)  // [128k][384n]
{
    int n = blockIdx.x;
    int k = threadIdx.x;
    float v = w_h[(size_t)k * GG + n];
    __nv_bfloat16 h = __float2bfloat16(v);
    g_whh_hi[n * HH + k] = h;
    g_whh_lo[n * HH + k] = __float2bfloat16(v - __bfloat162float(h));
}

// ============================================================================
// Kernel 3 (v10, unchanged): gx via fused 3-term mma.sync, K-split staging.
// ============================================================================
#define GXK_A_HI  0
#define GXK_A_LO  16384
#define GXK_B_HI  32768
#define GXK_B_LO  49152
#define GXK_SMEM  65536

__global__ void __launch_bounds__(256, 2) gx_mma_kernel(
    const float* __restrict__ x,     // [B][T][128] == [m][128]
    const float* __restrict__ bvec)  // [384]
{
    extern __shared__ char smemc[];
    const int tid  = threadIdx.x;
    const int wid  = tid >> 5;
    const int lane = tid & 31;
    const int gate = blockIdx.x % 3;
    const int m0g  = (blockIdx.x / 3) * 128;
    uint32_t sbase = smem_u32(smemc);

    const int m0w = (wid & 3) * 32;
    const int n0w = (wid >> 2) * 64;
    const int lr  = lane & 15;
    const int lc  = lane >> 4;

    float acc[2][8][4];
    #pragma unroll
    for (int mi = 0; mi < 2; mi++)
        #pragma unroll
        for (int nt = 0; nt < 8; nt++)
            #pragma unroll
            for (int q = 0; q < 4; q++) acc[mi][nt][q] = 0.0f;

    const int srow = tid >> 1;
    const int shalf = tid & 1;

    #pragma unroll 1
    for (int ph = 0; ph < 2; ph++) {
        {
            size_t src = (size_t)(gate * 128 + srow) * INDIM + ph * 64 + shalf * 32;
            const char* bh = (const char*)(g_whi + src);
            const char* bl = (const char*)(g_wlo + src);
            #pragma unroll
            for (int u = 0; u < 4; u++) {
                uint32_t o = swz128(srow, shalf * 4 + u);
                cp_async16(sbase + GXK_B_HI + o, bh + u * 16);
                cp_async16(sbase + GXK_B_LO + o, bl + u * 16);
            }
            asm volatile("cp.async.commit_group;" ::: "memory");
        }
        {
            const float4* xr = (const float4*)(x + (size_t)(m0g + srow) * INDIM
                                               + ph * 64 + shalf * 32);
            #pragma unroll
            for (int u = 0; u < 4; u++) {
                float4 a = xr[2 * u], b = xr[2 * u + 1];
                float f[8] = {a.x, a.y, a.z, a.w, b.x, b.y, b.z, b.w};
                uint32_t hi[4], lo[4];
                #pragma unroll
                for (int p = 0; p < 4; p++) {
                    __nv_bfloat162 h = __floats2bfloat162_rn(f[2*p], f[2*p+1]);
                    hi[p] = *(uint32_t*)&h;
                    float l0 = f[2*p]     - __bfloat162float(h.x);
                    float l1 = f[2*p + 1] - __bfloat162float(h.y);
                    __nv_bfloat162 l = __floats2bfloat162_rn(l0, l1);
                    lo[p] = *(uint32_t*)&l;
                }
                uint32_t o = swz128(srow, shalf * 4 + u);
                *(uint4*)(smemc + GXK_A_HI + o) = make_uint4(hi[0], hi[1], hi[2], hi[3]);
                *(uint4*)(smemc + GXK_A_LO + o) = make_uint4(lo[0], lo[1], lo[2], lo[3]);
            }
        }
        asm volatile("cp.async.wait_group 0;" ::: "memory");
        __syncthreads();

        #pragma unroll
        for (int s = 0; s < 4; s++) {
            const int c16 = 2 * s + lc;
            const int ra  = m0w + lr;

            uint32_t a0[4], a1[4];
            ldsm_x4(a0, sbase + GXK_A_HI + swz128(ra, c16));
            ldsm_x4(a1, sbase + GXK_A_HI + swz128(ra + 16, c16));

            uint32_t bh[4][4];
            #pragma unroll
            for (int q = 0; q < 4; q++)
                ldsm_x4(bh[q], sbase + GXK_B_HI + swz128(n0w + q * 16 + lr, c16));

            #pragma unroll
            for (int nt = 0; nt < 8; nt++) {
                int q = nt >> 1, sel = nt & 1;
                mma_bf16(acc[0][nt], a0, bh[q][sel], bh[q][sel + 2]);
                mma_bf16(acc[1][nt], a1, bh[q][sel], bh[q][sel + 2]);
            }
            {
                uint32_t bl[4][4];
                #pragma unroll
                for (int q = 0; q < 4; q++)
                    ldsm_x4(bl[q], sbase + GXK_B_LO + swz128(n0w + q * 16 + lr, c16));
                #pragma unroll
                for (int nt = 0; nt < 8; nt++) {
                    int q = nt >> 1, sel = nt & 1;
                    mma_bf16(acc[0][nt], a0, bl[q][sel], bl[q][sel + 2]);
                    mma_bf16(acc[1][nt], a1, bl[q][sel], bl[q][sel + 2]);
                }
            }
            {
                uint32_t l0[4], l1[4];
                ldsm_x4(l0, sbase + GXK_A_LO + swz128(ra, c16));
                ldsm_x4(l1, sbase + GXK_A_LO + swz128(ra + 16, c16));
                #pragma unroll
                for (int nt = 0; nt < 8; nt++) {
                    int q = nt >> 1, sel = nt & 1;
                    mma_bf16(acc[0][nt], l0, bh[q][sel], bh[q][sel + 2]);
                    mma_bf16(acc[1][nt], l1, bh[q][sel], bh[q][sel + 2]);
                }
            }
        }
        if (ph == 0) __syncthreads();
    }

    const int colq = (lane & 3) * 2;
    #pragma unroll
    for (int nt = 0; nt < 8; nt++) {
        int c = n0w + nt * 8 + colq;
        float2 bv = *(const float2*)(bvec + gate * 128 + c);
        #pragma unroll
        for (int mi = 0; mi < 2; mi++) {
            int gm0 = m0g + m0w + 16 * mi + (lane >> 2);
            #pragma unroll
            for (int h = 0; h < 2; h++) {
                int gm = gm0 + 8 * h;
                int tt = gm & 255, bb = gm >> 8;
                float2 o;
                o.x = acc[mi][nt][2 * h + 0] + bv.x;
                o.y = acc[mi][nt][2 * h + 1] + bv.y;
                *(float2*)(g_gx + ((size_t)tt * BB + bb) * GG + gate * 128 + c) = o;
            }
        }
    }
}

// ============================================================================
// Kernel 4 (v11 = rec_tc4): tensor-core recurrence with STACKED hi/lo A tiles.
// A tile rows 0-7 = value_hi, rows 8-15 = value_lo (same batch rows). One mma
// vs B=w_hi gives hh (d[0,1]) AND lh (d[2,3]); one vs B=w_lo gives hl AND ll.
// Epilogue: d[0]+d[2]. 3-term -> 2 mma per (s,nt): 72 -> 48 mma/warp/step,
// and the ll term comes free (slightly better accuracy).
// 128 CTAs x 512 thr, 8 rows/CTA, whh bf16 hi/lo static in smem.
// ============================================================================
#define RT_B_HI  0          // 384*256 = 98304
#define RT_B_LO  98304
#define RT_HST   196608     // stacked h tile 16x128 bf16 = 4096
#define RT_RST   200704     // stacked rh tile
#define RT_H32   204800     // 8*128 f32 = 4096
#define RT_ZS    208896     // 128*8 f32 = 4096
#define RT_SMEM  212992

__global__ void __launch_bounds__(512, 1) rec_tc_kernel()
{
    extern __shared__ char smemc[];
    uint32_t sb = smem_u32(smemc);
    float* h32 = (float*)(smemc + RT_H32);
    float* zsf = (float*)(smemc + RT_ZS);
    const int tid  = threadIdx.x;
    const int wid  = tid >> 5;
    const int lane = tid & 31;
    const int b0   = blockIdx.x * 8;

    // ---- stage static B = whh hi/lo, swizzled (rows 384 x 256B) ----
    for (int idx = tid; idx < 384 * 16; idx += 512) {
        int r = idx >> 4, c = idx & 15;
        uint32_t o = swz(r, c);
        cp_async16(sb + RT_B_HI + o, (const char*)g_whh_hi + (size_t)r * 256 + c * 16);
        cp_async16(sb + RT_B_LO + o, (const char*)g_whh_lo + (size_t)r * 256 + c * 16);
    }
    asm volatile("cp.async.commit_group;" ::: "memory");
    for (int idx = tid; idx < 1024; idx += 512) {
        ((uint32_t*)(smemc + RT_HST))[idx] = 0;
        ((uint32_t*)(smemc + RT_RST))[idx] = 0;
        h32[idx] = 0.0f;
    }
    asm volatile("cp.async.wait_group 0;" ::: "memory");
    __syncthreads();

    const int lr    = lane & 15;
    const int lc    = lane >> 4;
    const int lane8 = lane & 7;
    const int ksel  = (lane >> 3) & 1;   // x2 chunk selector
    const int row   = lane >> 2;
    const int cp2   = 2 * (lane & 3);
    const int n0z   = wid * 16;
    const int n0a   = 256 + wid * 8;
    const int acol  = wid * 8 + cp2;
    const int jz    = n0z - 128;

    // gx pipeline registers
    float2 gz0, gz1, ga;
    {
        const float* g0 = g_gx + (size_t)b0 * GG;
        gz0 = *(const float2*)(g0 + row * GG + n0z + cp2);
        gz1 = *(const float2*)(g0 + row * GG + n0z + 8 + cp2);
        ga  = *(const float2*)(g0 + row * GG + 256 + acol);
    }

    for (int t = 0; t < TT; t++) {
        // ---- zr MMA on stacked A: 2 mma per (s,nt) ----
        float az[2][4];
        #pragma unroll
        for (int nt = 0; nt < 2; nt++)
            #pragma unroll
            for (int q = 0; q < 4; q++) az[nt][q] = 0.0f;

        #pragma unroll
        for (int s = 0; s < 8; s++) {
            int c16 = 2 * s + lc;
            uint32_t A[4], Bh[4], Bl[4];
            ldsm_x4(A,  sb + RT_HST  + swz(lr, c16));
            ldsm_x4(Bh, sb + RT_B_HI + swz(n0z + lr, c16));
            ldsm_x4(Bl, sb + RT_B_LO + swz(n0z + lr, c16));
            #pragma unroll
            for (int nt = 0; nt < 2; nt++) {
                mma_bf16(az[nt], A, Bh[nt], Bh[nt + 2]);   // hh (rows 0-7) + lh (8-15)
                mma_bf16(az[nt], A, Bl[nt], Bl[nt + 2]);   // hl (rows 0-7) + ll (8-15)
            }
        }
        {
            // combine hi-row and lo-row halves: d[0,1] + d[2,3]
            float v00 = (az[0][0] + az[0][2]) + gz0.x;
            float v01 = (az[0][1] + az[0][3]) + gz0.y;
            float v10 = (az[1][0] + az[1][2]) + gz1.x;
            float v11 = (az[1][1] + az[1][3]) + gz1.y;
            if (wid < 8) {                       // z gate
                zsf[(n0z + cp2)         * 8 + row] = sigmoid_f(v00);
                zsf[(n0z + cp2 + 1)     * 8 + row] = sigmoid_f(v01);
                zsf[(n0z + 8 + cp2)     * 8 + row] = sigmoid_f(v10);
                zsf[(n0z + 8 + cp2 + 1) * 8 + row] = sigmoid_f(v11);
            } else {                             // r gate -> rh = r .* h
                float2 h0 = *(const float2*)&h32[row * 128 + jz + cp2];
                float2 h1 = *(const float2*)&h32[row * 128 + jz + 8 + cp2];
                float r00 = sigmoid_f(v00) * h0.x, r01 = sigmoid_f(v01) * h0.y;
                float r10 = sigmoid_f(v10) * h1.x, r11 = sigmoid_f(v11) * h1.y;
                bsplit_store_stacked(smemc, RT_RST, row, jz + cp2,     r00, r01);
                bsplit_store_stacked(smemc, RT_RST, row, jz + 8 + cp2, r10, r11);
            }
        }
        __syncthreads();

        // prefetch gx for step t+1 (covered by phase-2 region)
        float2 gz0n, gz1n, gan;
        if (t + 1 < TT) {
            const float* gn = g_gx + ((size_t)(t + 1) * BB + b0) * GG;
            gz0n = *(const float2*)(gn + row * GG + n0z + cp2);
            gz1n = *(const float2*)(gn + row * GG + n0z + 8 + cp2);
            gan  = *(const float2*)(gn + row * GG + 256 + acol);
        }

        // ---- a-gate MMA on stacked rh: 2 mma per s ----
        float aa[4] = {0.0f, 0.0f, 0.0f, 0.0f};
        #pragma unroll
        for (int s = 0; s < 8; s++) {
            int c16 = 2 * s + lc;
            uint32_t R[4], Bh2[2], Bl2[2];
            ldsm_x4(R, sb + RT_RST + swz(lr, c16));
            uint32_t a2 = swz(n0a + lane8, 2 * s + ksel);
            ldsm_x2(Bh2, sb + RT_B_HI + a2);
            ldsm_x2(Bl2, sb + RT_B_LO + a2);
            mma_bf16(aa, R, Bh2[0], Bh2[1]);
            mma_bf16(aa, R, Bl2[0], Bl2[1]);
        }
        {
            float s0 = (aa[0] + aa[2]) + ga.x;
            float s1 = (aa[1] + aa[3]) + ga.y;
            float a0 = tanh_f(s0);
            float a1 = tanh_f(s1);
            float z0 = zsf[(acol)     * 8 + row];
            float z1 = zsf[(acol + 1) * 8 + row];
            float2 hv = *(const float2*)&h32[row * 128 + acol];
            float hn0 = fmaf(z0, a0 - hv.x, hv.x);
            float hn1 = fmaf(z1, a1 - hv.y, hv.y);
            *(float2*)&h32[row * 128 + acol] = make_float2(hn0, hn1);
            bsplit_store_stacked(smemc, RT_HST, row, acol, hn0, hn1);
            *(float2*)&g_ys[((size_t)t * BB + b0 + row) * HH + acol] = make_float2(hn0, hn1);
        }
        gz0 = gz0n; gz1 = gz1n; ga = gan;
        __syncthreads();
    }
}

// ============================================================================
// Kernel 5 (unchanged): out[b,p] = sum_t sum_j ys[t,b,j]*W2[t,j,p] + bias.
// ============================================================================
__global__ void __launch_bounds__(512, 1) fc_kernel(float* __restrict__ out)
{
    __shared__ float red[8 * HOR * 4];

    const int tid = threadIdx.x;
    const int j   = tid & 127;
    const int g   = tid >> 7;
    const int b0  = blockIdx.x * 8;
    const int lane = tid & 31;
    const int jblk = (j >> 5);

    u64 acc[2][12];
    #pragma unroll
    for (int u = 0; u < 2; u++)
        #pragma unroll
        for (int q = 0; q < 12; q++) acc[u][q] = 0ULL;

    #pragma unroll 2
    for (int t = 0; t < TT; t++) {
        const float* ysp = g_ys + ((size_t)t * BB + b0 + 2 * g) * HH + j;
        float y0 = __ldg(ysp);
        float y1 = __ldg(ysp + HH);
        const ulonglong2* wp = (const ulonglong2*)(g_W2 + ((size_t)t * HH + j) * HOR);
        ulonglong2 w0 = wp[0], w1 = wp[1], w2 = wp[2],
                   w3 = wp[3], w4 = wp[4], w5 = wp[5];
        u64 wq[12] = {w0.x, w0.y, w1.x, w1.y, w2.x, w2.y,
                      w3.x, w3.y, w4.x, w4.y, w5.x, w5.y};
        u64 y0d = dup2(y0), y1d = dup2(y1);
        #pragma unroll
        for (int q = 0; q < 12; q++) {
            ffma2(acc[0][q], y0d, wq[q]);
            ffma2(acc[1][q], y1d, wq[q]);
        }
    }

    #pragma unroll
    for (int u = 0; u < 2; u++)
        #pragma unroll
        for (int q = 0; q < 12; q++) {
            fadd2(acc[u][q], shfl_xor_u64(acc[u][q], 1));
            fadd2(acc[u][q], shfl_xor_u64(acc[u][q], 2));
            fadd2(acc[u][q], shfl_xor_u64(acc[u][q], 4));
            fadd2(acc[u][q], shfl_xor_u64(acc[u][q], 8));
            fadd2(acc[u][q], shfl_xor_u64(acc[u][q], 16));
        }

    if (lane == 0) {
        #pragma unroll
        for (int u = 0; u < 2; u++) {
            int rrow = 2 * g + u;
            #pragma unroll
            for (int q = 0; q < 12; q++) {
                float v0, v1;
                unpack2(acc[u][q], v0, v1);
                red[(rrow * HOR + 2 * q + 0) * 4 + jblk] = v0;
                red[(rrow * HOR + 2 * q + 1) * 4 + jblk] = v1;
            }
        }
    }
    __syncthreads();

    if (tid < 8 * HOR) {
        int rrow = tid / HOR;
        int p    = tid - rrow * HOR;
        const float* pp = red + (rrow * HOR + p) * 4;
        float s = ((pp[0] + pp[1]) + pp[2]) + pp[3];
        out[(size_t)(b0 + rrow) * HOR + p] = s + g_final_bias[p];
    }
}

// ============================================================================
// launch
// ============================================================================
extern "C" void kernel_launch(void* const* d_in, const int* in_sizes, int n_in,
                              void* d_out, int out_size)
{
    const float* x     = (const float*)d_in[0];
    const float* w_i   = (const float*)d_in[1];
    const float* w_h   = (const float*)d_in[2];
    const float* bvec  = (const float*)d_in[3];
    const float* mlp_w = (const float*)d_in[4];
    const float* mlp_b = (const float*)d_in[5];
    const float* fc_w  = (const float*)d_in[6];
    const float* fc_b  = (const float*)d_in[7];
    const float* out_w = (const float*)d_in[8];
    const float* out_b = (const float*)d_in[9];
    float* out = (float*)d_out;

    const int smem_w2 = (3072 + 12288 + 1024) * 4;   // 65536

    cudaFuncSetAttribute(w2_kernel,     cudaFuncAttributeMaxDynamicSharedMemorySize, smem_w2);
    cudaFuncSetAttribute(gx_mma_kernel, cudaFuncAttributeMaxDynamicSharedMemorySize, GXK_SMEM);
    cudaFuncSetAttribute(rec_tc_kernel, cudaFuncAttributeMaxDynamicSharedMemorySize, RT_SMEM);

    w2_kernel<<<TT, 256, smem_w2>>>(mlp_w, mlp_b, fc_w, out_w);
    bias_final_kernel<<<1, 32>>>(fc_b, out_w, out_b);
    wsplit_kernel<<<GG, 128>>>(w_i);
    whhsplit_kernel<<<GG, 128>>>(w_h);
    gx_mma_kernel<<<(BB * TT / 128) * 3, 256, GXK_SMEM>>>(x, bvec);
    rec_tc_kernel<<<BB / 8, 512, RT_SMEM>>>();
    fc_kernel<<<BB / 8, 512>>>(out);
}